// round 1
// baseline (speedup 1.0000x reference)
#include <cuda_runtime.h>
#include <cuda_bf16.h>

// Problem constants
#define B_   16
#define T_   8
#define KB_  64      // weight bank size
#define CO_  128
#define CI_  128
#define KH_  5
#define KW_  5
#define H_   64
#define W_   64
#define PAD_ 2
#define WELEMS (CO_*CI_*KH_*KW_)   // 409600 per bank entry / per example

// Scratch (allocation-free rule: __device__ globals)
__device__ float g_s[B_*KB_];                   // mean-over-T task features
__device__ float g_lp[(long)B_*WELEMS];         // per-example conv weights, 26.2 MB

// ---------------------------------------------------------------------------
// Kernel A: s[b,k] = mean_t tf[b,t,k]
// ---------------------------------------------------------------------------
__global__ void k_reduce(const float* __restrict__ tf) {
    int i = blockIdx.x * blockDim.x + threadIdx.x;
    if (i < B_*KB_) {
        int b = i >> 6, k = i & 63;
        float a = 0.f;
        #pragma unroll
        for (int t = 0; t < T_; t++) a += tf[(b*T_ + t)*KB_ + k];
        g_s[i] = a * (1.0f / T_);
    }
}

// ---------------------------------------------------------------------------
// Kernel B: lp[b, idx] = sum_k s[b,k] * W[k, idx]   (idx over 409600, float4)
// Memory-bound: read 105 MB of W once, accumulate all 16 b in registers.
// ---------------------------------------------------------------------------
__global__ __launch_bounds__(256) void k_wsum(const float* __restrict__ Wb) {
    __shared__ float ss[B_*KB_];
    int tid = threadIdx.x;
    for (int i = tid; i < B_*KB_; i += blockDim.x) ss[i] = g_s[i];
    __syncthreads();

    int idx4 = (blockIdx.x * blockDim.x + tid) * 4;
    if (idx4 >= WELEMS) return;

    float4 acc[B_];
    #pragma unroll
    for (int b = 0; b < B_; b++) acc[b] = make_float4(0.f, 0.f, 0.f, 0.f);

    #pragma unroll 4
    for (int k = 0; k < KB_; k++) {
        float4 wv = *(const float4*)(Wb + (long)k*WELEMS + idx4);
        #pragma unroll
        for (int b = 0; b < B_; b++) {
            float sv = ss[b*KB_ + k];
            acc[b].x += sv * wv.x;
            acc[b].y += sv * wv.y;
            acc[b].z += sv * wv.z;
            acc[b].w += sv * wv.w;
        }
    }
    #pragma unroll
    for (int b = 0; b < B_; b++)
        *(float4*)(g_lp + (long)b*WELEMS + idx4) = acc[b];
}

// ---------------------------------------------------------------------------
// Kernel C: per-example 5x5 conv, pad 2.
// Block tile: 64 couts x (8x16 pixels). 256 threads, each 8 co x 4 px.
// K-loop over cin in chunks of 4, all 25 taps per cin.
// ---------------------------------------------------------------------------
#define TH_ 8
#define TWD 16
#define COT 64
#define CC_ 4

__global__ __launch_bounds__(256) void k_conv(const float* __restrict__ x,
                                              float* __restrict__ y) {
    __shared__ float xs[CC_][TH_+4][TWD+5];   // [4][12][21], row pad -> low conflicts
    __shared__ float ws[CC_*25][COT + 4];     // [100][68], 272B rows: 16B aligned

    const int tid   = threadIdx.x;
    const int cog   = tid >> 5;          // warp id = cout group (8 couts)
    const int lane  = tid & 31;
    const int col   = lane & 15;         // pixel column within tile
    const int rhalf = lane >> 4;         // 0/1 -> rows 0-3 / 4-7
    const int rbase = rhalf * 4;

    const int st   = blockIdx.x;         // 32 spatial tiles (fastest -> L2 w reuse)
    const int h0   = (st >> 2) * TH_;
    const int w0   = (st & 3)  * TWD;
    const int co0  = blockIdx.y * COT;   // 0 or 64
    const int b    = blockIdx.z;

    const float* xb  = x    + ((long)b*CI_)*H_*W_;
    const float* lpb = g_lp + (long)b*WELEMS;

    float acc[4][8];
    #pragma unroll
    for (int k = 0; k < 4; k++)
        #pragma unroll
        for (int j = 0; j < 8; j++) acc[k][j] = 0.f;

    for (int cc0 = 0; cc0 < CI_; cc0 += CC_) {
        // ---- stage x halo tile: CC_ x 12 x 20 ----
        for (int i = tid; i < CC_*12*20; i += 256) {
            int c   = i / 240;
            int rem = i - c*240;
            int r   = rem / 20;
            int cw  = rem - r*20;
            int gh  = h0 + r  - PAD_;
            int gw  = w0 + cw - PAD_;
            float v = 0.f;
            if ((unsigned)gh < H_ && (unsigned)gw < W_)
                v = xb[((cc0 + c)*H_ + gh)*W_ + gw];
            xs[c][r][cw] = v;
        }
        // ---- stage weights transposed: [cin*25][co] ----
        for (int i = tid; i < COT*CC_*25; i += 256) {
            int co = i / (CC_*25);
            int j  = i - co*(CC_*25);           // j = cin_local*25 + tap
            ws[j][co] = lpb[((co0 + co)*CI_ + cc0 + (j/25))*25 + (j % 25)];
        }
        __syncthreads();

        // ---- compute ----
        #pragma unroll
        for (int c = 0; c < CC_; c++) {
            #pragma unroll
            for (int dh = 0; dh < KH_; dh++) {
                #pragma unroll
                for (int dw = 0; dw < KW_; dw++) {
                    const float* wr = &ws[c*25 + dh*5 + dw][cog*8];
                    float4 wa = *(const float4*)(wr);
                    float4 wb2 = *(const float4*)(wr + 4);
                    #pragma unroll
                    for (int k = 0; k < 4; k++) {
                        float xv = xs[c][rbase + k + dh][col + dw];
                        acc[k][0] += xv * wa.x;
                        acc[k][1] += xv * wa.y;
                        acc[k][2] += xv * wa.z;
                        acc[k][3] += xv * wa.w;
                        acc[k][4] += xv * wb2.x;
                        acc[k][5] += xv * wb2.y;
                        acc[k][6] += xv * wb2.z;
                        acc[k][7] += xv * wb2.w;
                    }
                }
            }
        }
        __syncthreads();
    }

    // ---- write out ----
    #pragma unroll
    for (int j = 0; j < 8; j++) {
        int co = co0 + cog*8 + j;
        #pragma unroll
        for (int k = 0; k < 4; k++) {
            int gh = h0 + rbase + k;
            y[(((long)b*CO_ + co)*H_ + gh)*W_ + w0 + col] = acc[k][j];
        }
    }
}

// ---------------------------------------------------------------------------
// Launch
// ---------------------------------------------------------------------------
extern "C" void kernel_launch(void* const* d_in, const int* in_sizes, int n_in,
                              void* d_out, int out_size) {
    const float* x  = (const float*)d_in[0];  // (16,128,64,64)
    const float* tf = (const float*)d_in[1];  // (16,8,64)
    const float* Wb = (const float*)d_in[2];  // (64,128,128,5,5)
    float* y        = (float*)d_out;          // (16,128,64,64)

    k_reduce<<<1, 1024>>>(tf);
    k_wsum<<<(WELEMS/4 + 255)/256, 256>>>(Wb);
    dim3 grid(32, 2, B_);
    k_conv<<<grid, 256>>>(x, y);
    (void)in_sizes; (void)n_in; (void)out_size;
}

// round 2
// speedup vs baseline: 2.7710x; 2.7710x over previous
#include <cuda_runtime.h>
#include <cuda_bf16.h>
#include <cstdint>

// Problem constants
#define B_   16
#define T_   8
#define KB_  64
#define CO_  128
#define CI_  128
#define KH_  5
#define KW_  5
#define H_   64
#define W_   64
#define PAD_ 2
#define WELEMS (CO_*CI_*KH_*KW_)   // 409600

// Scratch (allocation-free rule)
__device__ float g_s[B_*KB_];
__device__ float g_lp[(long)B_*WELEMS];   // 26.2 MB, fits in L2

// ---------------------------------------------------------------------------
// Kernel A: s[b,k] = mean_t tf[b,t,k]
// ---------------------------------------------------------------------------
__global__ void k_reduce(const float* __restrict__ tf) {
    int i = blockIdx.x * blockDim.x + threadIdx.x;
    if (i < B_*KB_) {
        int b = i >> 6, k = i & 63;
        float a = 0.f;
        #pragma unroll
        for (int t = 0; t < T_; t++) a += tf[(b*T_ + t)*KB_ + k];
        g_s[i] = a * (1.0f / T_);
    }
}

// ---------------------------------------------------------------------------
// Kernel B: lp[b, idx] = sum_k s[b,k] * W[k, idx]   (memory-bound, 105 MB read)
// ---------------------------------------------------------------------------
__global__ __launch_bounds__(256) void k_wsum(const float* __restrict__ Wb) {
    __shared__ float ss[B_*KB_];
    int tid = threadIdx.x;
    for (int i = tid; i < B_*KB_; i += blockDim.x) ss[i] = g_s[i];
    __syncthreads();

    int idx4 = (blockIdx.x * blockDim.x + tid) * 4;
    if (idx4 >= WELEMS) return;

    float4 acc[B_];
    #pragma unroll
    for (int b = 0; b < B_; b++) acc[b] = make_float4(0.f, 0.f, 0.f, 0.f);

    #pragma unroll 4
    for (int k = 0; k < KB_; k++) {
        float4 wv = *(const float4*)(Wb + (long)k*WELEMS + idx4);
        #pragma unroll
        for (int b = 0; b < B_; b++) {
            float sv = ss[b*KB_ + k];
            acc[b].x += sv * wv.x;
            acc[b].y += sv * wv.y;
            acc[b].z += sv * wv.z;
            acc[b].w += sv * wv.w;
        }
    }
    #pragma unroll
    for (int b = 0; b < B_; b++)
        *(float4*)(g_lp + (long)b*WELEMS + idx4) = acc[b];
}

// ---------------------------------------------------------------------------
// Kernel C: tf32 tensor-core conv. 25 shifted GEMMs, K-chunks of 8 ci.
//
// CTA tile: 64 cout x 256 px (4 image rows). 8 warps, warp tile 64co x 32px.
// Per ci-block of 8: stage x slab [8ci][8 rows][68 cols] and weight slab
// [8ci][25 tap][64co] in SMEM (tf32-rounded), then 25 k-steps of m16n8k8.
//
// SMEM padding chosen so both A and B fragment loads are bank-conflict-free:
//   ws ci-stride = 25*72 = 1800 = 8 (mod 32);  xs ci-stride = 552 = 8 (mod 32)
//   -> lane bank = 8*tig + g covers 0..31.
// ---------------------------------------------------------------------------
#define KC_    8
#define WS_P   72                       // padded co dim
#define WS_CI  (25*WS_P)                // 1800 floats per ci
#define WS_FLOATS (KC_*WS_CI)           // 14400
#define XS_CI  (8*68 + 8)               // 552 floats per ci (8 rows * 68 + pad)
#define XS_FLOATS (KC_*XS_CI)           // 4416
#define SMEM_U32 (WS_FLOATS + XS_FLOATS)

__device__ __forceinline__ unsigned f2tf(float f) {
    unsigned u;
    asm("cvt.rna.tf32.f32 %0, %1;" : "=r"(u) : "f"(f));
    return u;
}

__device__ __forceinline__ void mma8(float& d0, float& d1, float& d2, float& d3,
                                     unsigned a0, unsigned a1, unsigned a2, unsigned a3,
                                     unsigned b0, unsigned b1) {
    asm volatile("mma.sync.aligned.m16n8k8.row.col.f32.tf32.tf32.f32 "
                 "{%0,%1,%2,%3}, {%4,%5,%6,%7}, {%8,%9}, {%0,%1,%2,%3};"
                 : "+f"(d0), "+f"(d1), "+f"(d2), "+f"(d3)
                 : "r"(a0), "r"(a1), "r"(a2), "r"(a3), "r"(b0), "r"(b1));
}

__global__ __launch_bounds__(256, 2) void k_conv(const float* __restrict__ x,
                                                 float* __restrict__ y) {
    extern __shared__ unsigned smem[];
    unsigned* WS = smem;                 // [8ci][25tap][72(co pad)]
    unsigned* XS = smem + WS_FLOATS;     // [8ci][8row*68 + pad]

    const int tid  = threadIdx.x;
    const int lane = tid & 31;
    const int w    = tid >> 5;
    const int g    = lane >> 2;          // groupID
    const int tig  = lane & 3;           // thread-in-group

    const int h0  = blockIdx.x * 4;      // 4 image rows per CTA
    const int co0 = blockIdx.y * 64;
    const int b   = blockIdx.z;

    const int wr = w >> 1;               // warp image row (0..3)
    const int cw = (w & 1) * 32;         // warp col base (0/32)

    const float* xb  = x + ((long)b*CI_)*H_*W_;
    const float* lpb = g_lp + (long)b*WELEMS + (long)co0*CI_*25;

    const int aBase = tig*WS_CI + g;           // + tap*72 + 16*mf (+8) (+4*WS_CI)
    const int bBase = tig*XS_CI + wr*68 + cw + g;  // + dh*68 + dw + 8*f (+4*XS_CI)

    float acc[4][4][4];
    #pragma unroll
    for (int mf = 0; mf < 4; mf++)
        #pragma unroll
        for (int f = 0; f < 4; f++)
            #pragma unroll
            for (int r = 0; r < 4; r++) acc[mf][f][r] = 0.f;

    for (int ci0 = 0; ci0 < CI_; ci0 += KC_) {
        __syncthreads();
        // ---- stage x slab: rows h0-2 .. h0+5, cols -2 .. 65 (zero OOB) ----
        for (int e = tid; e < KC_*8*68; e += 256) {
            int ci  = e / 544;
            int rem = e - ci*544;
            int r   = rem / 68;
            int c   = rem - r*68;
            int gh  = h0 - 2 + r;
            int gw  = c - 2;
            float v = 0.f;
            if ((unsigned)gh < H_ && (unsigned)gw < W_)
                v = xb[((ci0 + ci)*H_ + gh)*W_ + gw];
            XS[ci*XS_CI + r*68 + c] = f2tf(v);
        }
        // ---- stage weights: [64co][8ci][25tap] global -> ws[ci][tap][co] ----
        // global runs of 200 contiguous floats per co -> coalesced
        for (int e = tid; e < 64*KC_*25; e += 256) {
            int co = e / 200;
            int j  = e - co*200;          // ci*25 + tap
            int ci = j / 25;
            int tp = j - ci*25;
            float v = lpb[co*(CI_*25) + ci0*25 + j];
            WS[ci*WS_CI + tp*WS_P + co] = f2tf(v);
        }
        __syncthreads();

        // ---- 25 taps x (k=8 ci) MMA ----
        #pragma unroll
        for (int dh = 0; dh < KH_; dh++) {
            #pragma unroll
            for (int dw = 0; dw < KW_; dw++) {
                const int tap = dh*5 + dw;
                unsigned areg[4][4];
                const int aOff = aBase + tap*WS_P;
                #pragma unroll
                for (int mf = 0; mf < 4; mf++) {
                    areg[mf][0] = WS[aOff + 16*mf];
                    areg[mf][1] = WS[aOff + 16*mf + 8];
                    areg[mf][2] = WS[aOff + 16*mf + 4*WS_CI];
                    areg[mf][3] = WS[aOff + 16*mf + 4*WS_CI + 8];
                }
                unsigned breg[4][2];
                const int bOff = bBase + dh*68 + dw;
                #pragma unroll
                for (int f = 0; f < 4; f++) {
                    breg[f][0] = XS[bOff + 8*f];
                    breg[f][1] = XS[bOff + 8*f + 4*XS_CI];
                }
                #pragma unroll
                for (int mf = 0; mf < 4; mf++)
                    #pragma unroll
                    for (int f = 0; f < 4; f++)
                        mma8(acc[mf][f][0], acc[mf][f][1], acc[mf][f][2], acc[mf][f][3],
                             areg[mf][0], areg[mf][1], areg[mf][2], areg[mf][3],
                             breg[f][0], breg[f][1]);
            }
        }
    }

    // ---- write out ----
    const int hw = h0 + wr;
    #pragma unroll
    for (int mf = 0; mf < 4; mf++) {
        #pragma unroll
        for (int f = 0; f < 4; f++) {
            int co = co0 + 16*mf + g;
            int px = cw + 8*f + 2*tig;
            float* yp = y + (((long)b*CO_ + co)*H_ + hw)*W_ + px;
            yp[0] = acc[mf][f][0];
            yp[1] = acc[mf][f][1];
            yp[8*H_*W_ + 0] = acc[mf][f][2];   // co + 8
            yp[8*H_*W_ + 1] = acc[mf][f][3];
        }
    }
}

// ---------------------------------------------------------------------------
// Launch
// ---------------------------------------------------------------------------
extern "C" void kernel_launch(void* const* d_in, const int* in_sizes, int n_in,
                              void* d_out, int out_size) {
    const float* x  = (const float*)d_in[0];
    const float* tf = (const float*)d_in[1];
    const float* Wb = (const float*)d_in[2];
    float* y        = (float*)d_out;

    cudaFuncSetAttribute(k_conv, cudaFuncAttributeMaxDynamicSharedMemorySize,
                         SMEM_U32 * (int)sizeof(unsigned));

    k_reduce<<<1, 1024>>>(tf);
    k_wsum<<<(WELEMS/4 + 255)/256, 256>>>(Wb);
    dim3 grid(16, 2, B_);   // 16 row-quads x 2 co-halves x 16 examples
    k_conv<<<grid, 256, SMEM_U32 * (int)sizeof(unsigned)>>>(x, y);
    (void)in_sizes; (void)n_in; (void)out_size;
}

// round 3
// speedup vs baseline: 2.7931x; 1.0080x over previous
#include <cuda_runtime.h>
#include <cuda_bf16.h>
#include <cstdint>

// Problem constants
#define B_   16
#define T_   8
#define KB_  64
#define CO_  128
#define CI_  128
#define KH_  5
#define KW_  5
#define H_   64
#define W_   64
#define PAD_ 2
#define WELEMS (CO_*CI_*KH_*KW_)   // 409600

// Scratch (allocation-free rule)
__device__ float g_s[B_*KB_];
__device__ float g_lp[(long)B_*WELEMS];   // 26.2 MB, fits in L2

// ---------------------------------------------------------------------------
// Kernel A: s[b,k] = mean_t tf[b,t,k]
// ---------------------------------------------------------------------------
__global__ void k_reduce(const float* __restrict__ tf) {
    int i = blockIdx.x * blockDim.x + threadIdx.x;
    if (i < B_*KB_) {
        int b = i >> 6, k = i & 63;
        float a = 0.f;
        #pragma unroll
        for (int t = 0; t < T_; t++) a += tf[(b*T_ + t)*KB_ + k];
        g_s[i] = a * (1.0f / T_);
    }
}

// ---------------------------------------------------------------------------
// Kernel B: lp[b, idx] = sum_k s[b,k] * W[k, idx]   (memory-bound, 105 MB read)
// ---------------------------------------------------------------------------
__global__ __launch_bounds__(256) void k_wsum(const float* __restrict__ Wb) {
    __shared__ float ss[B_*KB_];
    int tid = threadIdx.x;
    for (int i = tid; i < B_*KB_; i += blockDim.x) ss[i] = g_s[i];
    __syncthreads();

    int idx4 = (blockIdx.x * blockDim.x + tid) * 4;
    if (idx4 >= WELEMS) return;

    float4 acc[B_];
    #pragma unroll
    for (int b = 0; b < B_; b++) acc[b] = make_float4(0.f, 0.f, 0.f, 0.f);

    #pragma unroll 4
    for (int k = 0; k < KB_; k++) {
        float4 wv = *(const float4*)(Wb + (long)k*WELEMS + idx4);
        #pragma unroll
        for (int b = 0; b < B_; b++) {
            float sv = ss[b*KB_ + k];
            acc[b].x += sv * wv.x;
            acc[b].y += sv * wv.y;
            acc[b].z += sv * wv.z;
            acc[b].w += sv * wv.w;
        }
    }
    #pragma unroll
    for (int b = 0; b < B_; b++)
        *(float4*)(g_lp + (long)b*WELEMS + idx4) = acc[b];
}

// ---------------------------------------------------------------------------
// Kernel C: tf32 tensor-core conv. 25 shifted GEMMs, K-chunks of 8 ci.
//
// CTA tile: 64 cout x 256 px (4 image rows). 8 warps, warp tile 64co x 32px.
// Per ci-block of 8: stage x slab [8ci][8 rows][68 cols] and weight slab
// [8ci][25 tap][64co] in SMEM (tf32-rounded), then 25 k-steps of m16n8k8.
//
// SMEM padding chosen so both A and B fragment loads are bank-conflict-free:
//   ws ci-stride = 25*72 = 1800 = 8 (mod 32);  xs ci-stride = 552 = 8 (mod 32)
//   -> lane bank = 8*tig + g covers 0..31.
// ---------------------------------------------------------------------------
#define KC_    8
#define WS_P   72                       // padded co dim
#define WS_CI  (25*WS_P)                // 1800 floats per ci
#define WS_FLOATS (KC_*WS_CI)           // 14400
#define XS_CI  (8*68 + 8)               // 552 floats per ci (8 rows * 68 + pad)
#define XS_FLOATS (KC_*XS_CI)           // 4416
#define SMEM_U32 (WS_FLOATS + XS_FLOATS)

__device__ __forceinline__ unsigned f2tf(float f) {
    unsigned u;
    asm("cvt.rna.tf32.f32 %0, %1;" : "=r"(u) : "f"(f));
    return u;
}

__device__ __forceinline__ void mma8(float& d0, float& d1, float& d2, float& d3,
                                     unsigned a0, unsigned a1, unsigned a2, unsigned a3,
                                     unsigned b0, unsigned b1) {
    asm volatile("mma.sync.aligned.m16n8k8.row.col.f32.tf32.tf32.f32 "
                 "{%0,%1,%2,%3}, {%4,%5,%6,%7}, {%8,%9}, {%0,%1,%2,%3};"
                 : "+f"(d0), "+f"(d1), "+f"(d2), "+f"(d3)
                 : "r"(a0), "r"(a1), "r"(a2), "r"(a3), "r"(b0), "r"(b1));
}

__global__ __launch_bounds__(256, 2) void k_conv(const float* __restrict__ x,
                                                 float* __restrict__ y) {
    extern __shared__ unsigned smem[];
    unsigned* WS = smem;                 // [8ci][25tap][72(co pad)]
    unsigned* XS = smem + WS_FLOATS;     // [8ci][8row*68 + pad]

    const int tid  = threadIdx.x;
    const int lane = tid & 31;
    const int w    = tid >> 5;
    const int g    = lane >> 2;          // groupID
    const int tig  = lane & 3;           // thread-in-group

    const int h0  = blockIdx.x * 4;      // 4 image rows per CTA
    const int co0 = blockIdx.y * 64;
    const int b   = blockIdx.z;

    const int wr = w >> 1;               // warp image row (0..3)
    const int cw = (w & 1) * 32;         // warp col base (0/32)

    const float* xb  = x + ((long)b*CI_)*H_*W_;
    const float* lpb = g_lp + (long)b*WELEMS + (long)co0*CI_*25;

    const int aBase = tig*WS_CI + g;           // + tap*72 + 16*mf (+8) (+4*WS_CI)
    const int bBase = tig*XS_CI + wr*68 + cw + g;  // + dh*68 + dw + 8*f (+4*XS_CI)

    float acc[4][4][4];
    #pragma unroll
    for (int mf = 0; mf < 4; mf++)
        #pragma unroll
        for (int f = 0; f < 4; f++)
            #pragma unroll
            for (int r = 0; r < 4; r++) acc[mf][f][r] = 0.f;

    for (int ci0 = 0; ci0 < CI_; ci0 += KC_) {
        __syncthreads();
        // ---- stage x slab: rows h0-2 .. h0+5, cols -2 .. 65 (zero OOB) ----
        for (int e = tid; e < KC_*8*68; e += 256) {
            int ci  = e / 544;
            int rem = e - ci*544;
            int r   = rem / 68;
            int c   = rem - r*68;
            int gh  = h0 - 2 + r;
            int gw  = c - 2;
            float v = 0.f;
            if ((unsigned)gh < H_ && (unsigned)gw < W_)
                v = xb[((ci0 + ci)*H_ + gh)*W_ + gw];
            XS[ci*XS_CI + r*68 + c] = f2tf(v);
        }
        // ---- stage weights: [64co][8ci][25tap] global -> ws[ci][tap][co] ----
        // global runs of 200 contiguous floats per co -> coalesced
        for (int e = tid; e < 64*KC_*25; e += 256) {
            int co = e / 200;
            int j  = e - co*200;          // ci*25 + tap
            int ci = j / 25;
            int tp = j - ci*25;
            float v = lpb[co*(CI_*25) + ci0*25 + j];
            WS[ci*WS_CI + tp*WS_P + co] = f2tf(v);
        }
        __syncthreads();

        // ---- 25 taps x (k=8 ci) MMA ----
        #pragma unroll
        for (int dh = 0; dh < KH_; dh++) {
            #pragma unroll
            for (int dw = 0; dw < KW_; dw++) {
                const int tap = dh*5 + dw;
                unsigned areg[4][4];
                const int aOff = aBase + tap*WS_P;
                #pragma unroll
                for (int mf = 0; mf < 4; mf++) {
                    areg[mf][0] = WS[aOff + 16*mf];
                    areg[mf][1] = WS[aOff + 16*mf + 8];
                    areg[mf][2] = WS[aOff + 16*mf + 4*WS_CI];
                    areg[mf][3] = WS[aOff + 16*mf + 4*WS_CI + 8];
                }
                unsigned breg[4][2];
                const int bOff = bBase + dh*68 + dw;
                #pragma unroll
                for (int f = 0; f < 4; f++) {
                    breg[f][0] = XS[bOff + 8*f];
                    breg[f][1] = XS[bOff + 8*f + 4*XS_CI];
                }
                #pragma unroll
                for (int mf = 0; mf < 4; mf++)
                    #pragma unroll
                    for (int f = 0; f < 4; f++)
                        mma8(acc[mf][f][0], acc[mf][f][1], acc[mf][f][2], acc[mf][f][3],
                             areg[mf][0], areg[mf][1], areg[mf][2], areg[mf][3],
                             breg[f][0], breg[f][1]);
            }
        }
    }

    // ---- write out ----
    const int hw = h0 + wr;
    #pragma unroll
    for (int mf = 0; mf < 4; mf++) {
        #pragma unroll
        for (int f = 0; f < 4; f++) {
            int co = co0 + 16*mf + g;
            int px = cw + 8*f + 2*tig;
            float* yp = y + (((long)b*CO_ + co)*H_ + hw)*W_ + px;
            yp[0] = acc[mf][f][0];
            yp[1] = acc[mf][f][1];
            yp[8*H_*W_ + 0] = acc[mf][f][2];   // co + 8
            yp[8*H_*W_ + 1] = acc[mf][f][3];
        }
    }
}

// ---------------------------------------------------------------------------
// Launch
// ---------------------------------------------------------------------------
extern "C" void kernel_launch(void* const* d_in, const int* in_sizes, int n_in,
                              void* d_out, int out_size) {
    const float* x  = (const float*)d_in[0];
    const float* tf = (const float*)d_in[1];
    const float* Wb = (const float*)d_in[2];
    float* y        = (float*)d_out;

    cudaFuncSetAttribute(k_conv, cudaFuncAttributeMaxDynamicSharedMemorySize,
                         SMEM_U32 * (int)sizeof(unsigned));

    k_reduce<<<1, 1024>>>(tf);
    k_wsum<<<(WELEMS/4 + 255)/256, 256>>>(Wb);
    dim3 grid(16, 2, B_);   // 16 row-quads x 2 co-halves x 16 examples
    k_conv<<<grid, 256, SMEM_U32 * (int)sizeof(unsigned)>>>(x, y);
    (void)in_sizes; (void)n_in; (void)out_size;
}

// round 5
// speedup vs baseline: 3.7631x; 1.3473x over previous
#include <cuda_runtime.h>
#include <cuda_fp16.h>
#include <cstdint>
#include <cstddef>

// Problem constants
#define B_   16
#define T_   8
#define KB_  64
#define CO_  128
#define CI_  128
#define H_   64
#define W_   64
#define WELEMS (CO_*CI_*25)          // 409600

// ---------------------------------------------------------------------------
// Scratch (__device__ globals; allocation-free rule)
// ---------------------------------------------------------------------------
__device__ float g_s[B_*KB_];                                      // mean-over-T tf
__device__ __align__(16) unsigned g_xh[(size_t)B_*64*H_*W_];       // half2 x planes [b][ci/2][h][w]
__device__ __align__(16) __half  g_lph[(size_t)B_*8*2*CO_*25*8];   // [b][cc][kk][co][tap][ci8]

// ---------------------------------------------------------------------------
// Kernel A: s[b,k] = mean_t tf[b,t,k]
// ---------------------------------------------------------------------------
__global__ void k_reduce(const float* __restrict__ tf) {
    int i = blockIdx.x * blockDim.x + threadIdx.x;
    if (i < B_*KB_) {
        int b = i >> 6, k = i & 63;
        float a = 0.f;
        #pragma unroll
        for (int t = 0; t < T_; t++) a += tf[(b*T_ + t)*KB_ + k];
        g_s[i] = a * (1.0f / T_);
    }
}

// ---------------------------------------------------------------------------
// Kernel X: pack x into half2 ci-pair planes.
// ---------------------------------------------------------------------------
__global__ __launch_bounds__(256) void k_xcvt(const float* __restrict__ x) {
    size_t i = (size_t)blockIdx.x * 256 + threadIdx.x;
    if (i >= (size_t)B_*64*H_*W_) return;
    int hw   = (int)(i & 4095);
    int rest = (int)(i >> 12);
    int pl   = rest & 63;
    int b    = rest >> 6;
    const float* xb = x + ((size_t)(b*CI_ + 2*pl))*4096 + hw;
    unsigned lo = __half_as_ushort(__float2half_rn(xb[0]));
    unsigned hi = __half_as_ushort(__float2half_rn(xb[4096]));
    g_xh[i] = lo | (hi << 16);
}

// ---------------------------------------------------------------------------
// Kernel B: weighted weight-bank sum -> fp16, emitted in MMA tile layout.
//   dst half index: ((((b*8+cc)*2+kk)*128+co)*25+tap)*8 + ci8
// Coalesced float4 reads of W; 16 examples accumulated in registers.
// ---------------------------------------------------------------------------
__global__ __launch_bounds__(256) void k_wsum(const float* __restrict__ Wb) {
    __shared__ float ss[B_*KB_];
    int tid = threadIdx.x;
    for (int i = tid; i < B_*KB_; i += 256) ss[i] = g_s[i];
    __syncthreads();

    int idx4 = (blockIdx.x * 256 + tid) * 4;
    if (idx4 >= WELEMS) return;

    float4 acc[B_];
    #pragma unroll
    for (int b = 0; b < B_; b++) acc[b] = make_float4(0.f, 0.f, 0.f, 0.f);

    #pragma unroll 4
    for (int k = 0; k < KB_; k++) {
        float4 wv = *(const float4*)(Wb + (size_t)k*WELEMS + idx4);
        #pragma unroll
        for (int b = 0; b < B_; b++) {
            float sv = ss[b*KB_ + k];
            acc[b].x += sv * wv.x;
            acc[b].y += sv * wv.y;
            acc[b].z += sv * wv.z;
            acc[b].w += sv * wv.w;
        }
    }

    #pragma unroll
    for (int j = 0; j < 4; j++) {
        int flat = idx4 + j;
        int tap  = flat % 25;
        int cr   = flat / 25;
        int ci   = cr & 127;
        int co   = cr >> 7;
        int cc   = ci >> 4;
        int kk   = (ci >> 3) & 1;
        int ci8  = ci & 7;
        #pragma unroll
        for (int b = 0; b < B_; b++) {
            float v = (j == 0) ? acc[b].x : (j == 1) ? acc[b].y : (j == 2) ? acc[b].z : acc[b].w;
            size_t o = (((((size_t)b*8 + cc)*2 + kk)*CO_ + co)*25 + tap)*8 + ci8;
            g_lph[o] = __float2half_rn(v);
        }
    }
}

// ---------------------------------------------------------------------------
// Kernel C: fp16 m16n8k16 conv, cp.async double-buffered.
// CTA: 512 thr (16 warps), tile 64co x (8 rows x 64 px). Warp: 64co x 32px.
// 8 chunks of 16 ci; per (chunk,tap): 4 ldmatrix.x4 + 8 LDS.32 + 16 MMA.
// ---------------------------------------------------------------------------
#define WS_TAPB   2048                        // bytes per tap (64co x 2 x 16B, swizzled)
#define WS_BYTES  (25*WS_TAPB)                // 51200 per buffer
#define XS_PLANE  888                         // half2 words per plane (12*72 + 24 pad)
#define XS_WORDS  (8*XS_PLANE)                // 7104 per buffer
#define XS_BYTES  (XS_WORDS*4)                // 28416
#define SMEM_BYTES (2*WS_BYTES + 2*XS_BYTES)  // 159232

__device__ __forceinline__ void cp16(void* dst, const void* src) {
    unsigned d = (unsigned)__cvta_generic_to_shared(dst);
    asm volatile("cp.async.cg.shared.global [%0], [%1], 16;" :: "r"(d), "l"(src));
}
__device__ __forceinline__ void ldsm4(unsigned* r, unsigned addr) {
    asm volatile("ldmatrix.sync.aligned.m8n8.x4.shared.b16 {%0,%1,%2,%3}, [%4];"
                 : "=r"(r[0]), "=r"(r[1]), "=r"(r[2]), "=r"(r[3]) : "r"(addr));
}
__device__ __forceinline__ void mma16(float* d, const unsigned* a, const unsigned* bb) {
    asm volatile("mma.sync.aligned.m16n8k16.row.col.f32.f16.f16.f32 "
                 "{%0,%1,%2,%3}, {%4,%5,%6,%7}, {%8,%9}, {%0,%1,%2,%3};"
                 : "+f"(d[0]), "+f"(d[1]), "+f"(d[2]), "+f"(d[3])
                 : "r"(a[0]), "r"(a[1]), "r"(a[2]), "r"(a[3]), "r"(bb[0]), "r"(bb[1]));
}

__global__ __launch_bounds__(512, 1) void k_conv(float* __restrict__ y) {
    extern __shared__ __align__(128) unsigned char smem[];
    unsigned char* WS = smem;                               // 2 swizzled weight buffers
    unsigned*      XS = (unsigned*)(smem + 2*WS_BYTES);     // 2 x-plane buffers

    const int tid = threadIdx.x;
    const int ln  = tid & 31;
    const int w   = tid >> 5;
    const int g   = ln >> 2;
    const int tig = ln & 3;
    const int wr  = w >> 1;              // output row within tile (0..7)
    const int cw  = (w & 1) * 32;        // column half

    const int h0  = blockIdx.x * 8;
    const int co0 = blockIdx.y * 64;
    const int b   = blockIdx.z;

    const unsigned ws_s = (unsigned)__cvta_generic_to_shared(WS);
    // per-lane ldmatrix offset within a tap slab (swizzled 16B chunk)
    const unsigned swzA = ((unsigned)(((ln & 15) << 1) | ((ln >> 4) ^ ((ln >> 2) & 1)))) << 4;

    // zero XS buffers once (halo edges + OOB rows stay zero for all chunks)
    for (int i = tid; i < 2*XS_WORDS; i += 512) XS[i] = 0;
    __syncthreads();

    auto stage = [&](int cc, int bufi) {
        // weights: 3200 x 16B, coalesced src (kk,co,tap order)
        unsigned char* wsb = WS + bufi*WS_BYTES;
        #pragma unroll 1
        for (int e = tid; e < 3200; e += 512) {
            int kk  = e / 1600;
            int r   = e - kk*1600;
            int co  = r / 25;
            int tap = r - co*25;
            const __half* src = g_lph +
                (((((size_t)b*8 + cc)*2 + kk)*CO_ + co0 + co)*25 + tap)*8;
            int swz = (co*2 + (kk ^ ((co >> 2) & 1)))*16;
            cp16(wsb + tap*WS_TAPB + swz, src);
        }
        // x planes: 8 planes x 12 halo rows x 16 chunks of 16B (skip OOB rows)
        unsigned* xsb = XS + bufi*XS_WORDS;
        #pragma unroll 1
        for (int e = tid; e < 1536; e += 512) {
            int pl  = e / 192;
            int rem = e - pl*192;
            int r   = rem >> 4;
            int q   = rem & 15;
            int gh  = h0 - 2 + r;
            if ((unsigned)gh < H_) {
                const unsigned* src = g_xh + (((size_t)(b*64 + cc*8 + pl)*64 + gh) << 6) + q*4;
                cp16(xsb + pl*XS_PLANE + r*72 + 4 + q*4, src);
            }
        }
    };

    float acc[4][4][4];
    #pragma unroll
    for (int mf = 0; mf < 4; mf++)
        #pragma unroll
        for (int f = 0; f < 4; f++)
            #pragma unroll
            for (int r = 0; r < 4; r++) acc[mf][f][r] = 0.f;

    stage(0, 0);
    asm volatile("cp.async.commit_group;");

    #pragma unroll 1
    for (int cc = 0; cc < 8; cc++) {
        const int bufi = cc & 1;
        if (cc < 7) {
            stage(cc + 1, (cc + 1) & 1);
            asm volatile("cp.async.commit_group;");
            asm volatile("cp.async.wait_group 1;");
        } else {
            asm volatile("cp.async.wait_group 0;");
        }
        __syncthreads();

        const unsigned  ws_buf = ws_s + bufi*WS_BYTES;
        const unsigned* xsb    = XS + bufi*XS_WORDS;
        const int xbase = wr*72 + 2 + cw + g;

        #pragma unroll
        for (int dh = 0; dh < 5; dh++) {
            #pragma unroll
            for (int dw = 0; dw < 5; dw++) {
                const int tap = dh*5 + dw;
                unsigned a[4][4];
                #pragma unroll
                for (int mf = 0; mf < 4; mf++)
                    ldsm4(a[mf], ws_buf + tap*WS_TAPB + swzA + mf*512);

                unsigned bb[4][2];
                const int xo = xbase + dh*72 + dw;
                #pragma unroll
                for (int f = 0; f < 4; f++) {
                    bb[f][0] = xsb[tig*XS_PLANE       + xo + 8*f];
                    bb[f][1] = xsb[(tig + 4)*XS_PLANE + xo + 8*f];
                }
                #pragma unroll
                for (int mf = 0; mf < 4; mf++)
                    #pragma unroll
                    for (int f = 0; f < 4; f++)
                        mma16(acc[mf][f], a[mf], bb[f]);
            }
        }
        __syncthreads();
    }

    // epilogue
    const int hw = h0 + wr;
    #pragma unroll
    for (int mf = 0; mf < 4; mf++) {
        #pragma unroll
        for (int f = 0; f < 4; f++) {
            int co = co0 + 16*mf + g;
            int px = cw + 8*f + 2*tig;
            float* yp = y + (((size_t)b*CO_ + co)*H_ + hw)*W_ + px;
            *(float2*)yp               = make_float2(acc[mf][f][0], acc[mf][f][1]);
            *(float2*)(yp + 8*H_*W_)   = make_float2(acc[mf][f][2], acc[mf][f][3]);
        }
    }
}

// ---------------------------------------------------------------------------
// Launch
// ---------------------------------------------------------------------------
extern "C" void kernel_launch(void* const* d_in, const int* in_sizes, int n_in,
                              void* d_out, int out_size) {
    const float* x  = (const float*)d_in[0];
    const float* tf = (const float*)d_in[1];
    const float* Wb = (const float*)d_in[2];
    float* y        = (float*)d_out;

    cudaFuncSetAttribute(k_conv, cudaFuncAttributeMaxDynamicSharedMemorySize, SMEM_BYTES);

    k_reduce<<<1, 1024>>>(tf);
    k_xcvt<<<(int)(((size_t)B_*64*H_*W_ + 255)/256), 256>>>(x);
    k_wsum<<<WELEMS/4/256, 256>>>(Wb);
    dim3 grid(8, 2, B_);
    k_conv<<<grid, 512, SMEM_BYTES>>>(y);
    (void)in_sizes; (void)n_in; (void)out_size;
}

// round 6
// speedup vs baseline: 5.9399x; 1.5784x over previous
#include <cuda_runtime.h>
#include <cuda_fp16.h>
#include <cstdint>
#include <cstddef>

// Problem constants
#define B_   16
#define T_   8
#define KB_  64
#define CO_  128
#define CI_  128
#define H_   64
#define W_   64
#define WELEMS (CO_*CI_*25)          // 409600

// ---------------------------------------------------------------------------
// Scratch (__device__ globals; allocation-free rule)
// ---------------------------------------------------------------------------
__device__ __align__(16) unsigned g_xh[(size_t)B_*64*H_*W_];       // half2 x planes [b][ci/2][h][w]
__device__ __align__(16) __half  g_lph[(size_t)B_*8*2*CO_*25*8];   // [b][cc][kk][co][tap][ci8]

// ---------------------------------------------------------------------------
// Kernel P: fused prep.
//  Blocks [0, 512): weighted weight-bank sum -> fp16 MMA-tile layout, with
//    in-block tf reduction and smem-transposed coalesced 16B writes.
//    Block = (co, ci-quarter of 32): 800 floats, k-loop 64, 16 b in regs.
//  Blocks [512, 1024): x fp32 -> half2 ci-pair planes, uint4 stores,
//    grid-stride. Runs CONCURRENTLY with the wsum blocks.
// ---------------------------------------------------------------------------
#define NWB 512
#define NXB 512

__global__ __launch_bounds__(256) void k_prep(const float* __restrict__ x,
                                              const float* __restrict__ tf,
                                              const float* __restrict__ Wb) {
    const int blk = blockIdx.x;
    const int tid = threadIdx.x;

    if (blk < NWB) {
        // ---------------- wsum part ----------------
        __shared__ float ss[B_*KB_];
        __shared__ __align__(16) float wbuf[800];

        for (int i = tid; i < B_*KB_; i += 256) {
            int b = i >> 6, k = i & 63;
            float a = 0.f;
            #pragma unroll
            for (int t = 0; t < T_; t++) a += tf[(b*T_ + t)*KB_ + k];
            ss[i] = a * (1.0f / T_);
        }
        __syncthreads();

        const int co = blk >> 2;
        const int q  = blk & 3;               // ci quarter (32 ci)
        const bool act = tid < 200;
        const float* src = Wb + co*3200 + q*800 + 4*tid;

        float4 acc[B_];
        #pragma unroll
        for (int b = 0; b < B_; b++) acc[b] = make_float4(0.f, 0.f, 0.f, 0.f);

        if (act) {
            #pragma unroll 4
            for (int k = 0; k < KB_; k++) {
                float4 wv = *(const float4*)(src + (size_t)k*WELEMS);
                #pragma unroll
                for (int b = 0; b < B_; b++) {
                    float sv = ss[b*KB_ + k];
                    acc[b].x += sv * wv.x;
                    acc[b].y += sv * wv.y;
                    acc[b].z += sv * wv.z;
                    acc[b].w += sv * wv.w;
                }
            }
        }

        // transpose per example through smem; emit coalesced 16B rows
        const int tap = tid % 25;
        const int c8  = tid / 25;             // ci8-block within quarter (0..3)
        #pragma unroll 1
        for (int b = 0; b < B_; b++) {
            if (act) *(float4*)(wbuf + 4*tid) = acc[b];
            __syncthreads();
            if (tid < 100) {
                __half h[8];
                #pragma unroll
                for (int i2 = 0; i2 < 8; i2++)
                    h[i2] = __float2half_rn(wbuf[(c8*8 + i2)*25 + tap]);
                int cc = q*2 + (c8 >> 1);
                int kk = c8 & 1;
                size_t o = (((((size_t)b*8 + cc)*2 + kk)*CO_ + co)*25 + tap)*8;
                *(uint4*)(g_lph + o) = *(const uint4*)h;
            }
            __syncthreads();
        }
    } else {
        // ---------------- xcvt part ----------------
        const size_t total4 = (size_t)B_*64*H_*W_ / 4;     // uint4 count
        for (size_t e = (size_t)(blk - NWB)*256 + tid; e < total4;
             e += (size_t)NXB*256) {
            size_t i = e * 4;
            int hw   = (int)(i & 4095);
            int rest = (int)(i >> 12);
            int pl   = rest & 63;
            int b    = rest >> 6;
            const float* xb = x + ((size_t)(b*CI_ + 2*pl))*4096 + hw;
            float4 lo = *(const float4*)xb;
            float4 hi = *(const float4*)(xb + 4096);
            uint4 o;
            __half2 p0 = __floats2half2_rn(lo.x, hi.x);
            __half2 p1 = __floats2half2_rn(lo.y, hi.y);
            __half2 p2 = __floats2half2_rn(lo.z, hi.z);
            __half2 p3 = __floats2half2_rn(lo.w, hi.w);
            o.x = *(unsigned*)&p0; o.y = *(unsigned*)&p1;
            o.z = *(unsigned*)&p2; o.w = *(unsigned*)&p3;
            *(uint4*)(g_xh + i) = o;
        }
    }
}

// ---------------------------------------------------------------------------
// Kernel C: fp16 m16n8k16 conv, cp.async double-buffered. (unchanged)
// ---------------------------------------------------------------------------
#define WS_TAPB   2048
#define WS_BYTES  (25*WS_TAPB)
#define XS_PLANE  888
#define XS_WORDS  (8*XS_PLANE)
#define XS_BYTES  (XS_WORDS*4)
#define SMEM_BYTES (2*WS_BYTES + 2*XS_BYTES)

__device__ __forceinline__ void cp16(void* dst, const void* src) {
    unsigned d = (unsigned)__cvta_generic_to_shared(dst);
    asm volatile("cp.async.cg.shared.global [%0], [%1], 16;" :: "r"(d), "l"(src));
}
__device__ __forceinline__ void ldsm4(unsigned* r, unsigned addr) {
    asm volatile("ldmatrix.sync.aligned.m8n8.x4.shared.b16 {%0,%1,%2,%3}, [%4];"
                 : "=r"(r[0]), "=r"(r[1]), "=r"(r[2]), "=r"(r[3]) : "r"(addr));
}
__device__ __forceinline__ void mma16(float* d, const unsigned* a, const unsigned* bb) {
    asm volatile("mma.sync.aligned.m16n8k16.row.col.f32.f16.f16.f32 "
                 "{%0,%1,%2,%3}, {%4,%5,%6,%7}, {%8,%9}, {%0,%1,%2,%3};"
                 : "+f"(d[0]), "+f"(d[1]), "+f"(d[2]), "+f"(d[3])
                 : "r"(a[0]), "r"(a[1]), "r"(a[2]), "r"(a[3]), "r"(bb[0]), "r"(bb[1]));
}

__global__ __launch_bounds__(512, 1) void k_conv(float* __restrict__ y) {
    extern __shared__ __align__(128) unsigned char smem[];
    unsigned char* WS = smem;
    unsigned*      XS = (unsigned*)(smem + 2*WS_BYTES);

    const int tid = threadIdx.x;
    const int ln  = tid & 31;
    const int w   = tid >> 5;
    const int g   = ln >> 2;
    const int tig = ln & 3;
    const int wr  = w >> 1;
    const int cw  = (w & 1) * 32;

    const int h0  = blockIdx.x * 8;
    const int co0 = blockIdx.y * 64;
    const int b   = blockIdx.z;

    const unsigned ws_s = (unsigned)__cvta_generic_to_shared(WS);
    const unsigned swzA = ((unsigned)(((ln & 15) << 1) | ((ln >> 4) ^ ((ln >> 2) & 1)))) << 4;

    for (int i = tid; i < 2*XS_WORDS; i += 512) XS[i] = 0;
    __syncthreads();

    auto stage = [&](int cc, int bufi) {
        unsigned char* wsb = WS + bufi*WS_BYTES;
        #pragma unroll 1
        for (int e = tid; e < 3200; e += 512) {
            int kk  = e / 1600;
            int r   = e - kk*1600;
            int co  = r / 25;
            int tap = r - co*25;
            const __half* src = g_lph +
                (((((size_t)b*8 + cc)*2 + kk)*CO_ + co0 + co)*25 + tap)*8;
            int swz = (co*2 + (kk ^ ((co >> 2) & 1)))*16;
            cp16(wsb + tap*WS_TAPB + swz, src);
        }
        unsigned* xsb = XS + bufi*XS_WORDS;
        #pragma unroll 1
        for (int e = tid; e < 1536; e += 512) {
            int pl  = e / 192;
            int rem = e - pl*192;
            int r   = rem >> 4;
            int q   = rem & 15;
            int gh  = h0 - 2 + r;
            if ((unsigned)gh < H_) {
                const unsigned* src = g_xh + (((size_t)(b*64 + cc*8 + pl)*64 + gh) << 6) + q*4;
                cp16(xsb + pl*XS_PLANE + r*72 + 4 + q*4, src);
            }
        }
    };

    float acc[4][4][4];
    #pragma unroll
    for (int mf = 0; mf < 4; mf++)
        #pragma unroll
        for (int f = 0; f < 4; f++)
            #pragma unroll
            for (int r = 0; r < 4; r++) acc[mf][f][r] = 0.f;

    stage(0, 0);
    asm volatile("cp.async.commit_group;");

    #pragma unroll 1
    for (int cc = 0; cc < 8; cc++) {
        const int bufi = cc & 1;
        if (cc < 7) {
            stage(cc + 1, (cc + 1) & 1);
            asm volatile("cp.async.commit_group;");
            asm volatile("cp.async.wait_group 1;");
        } else {
            asm volatile("cp.async.wait_group 0;");
        }
        __syncthreads();

        const unsigned  ws_buf = ws_s + bufi*WS_BYTES;
        const unsigned* xsb    = XS + bufi*XS_WORDS;
        const int xbase = wr*72 + 2 + cw + g;

        #pragma unroll
        for (int dh = 0; dh < 5; dh++) {
            #pragma unroll
            for (int dw = 0; dw < 5; dw++) {
                const int tap = dh*5 + dw;
                unsigned a[4][4];
                #pragma unroll
                for (int mf = 0; mf < 4; mf++)
                    ldsm4(a[mf], ws_buf + tap*WS_TAPB + swzA + mf*512);

                unsigned bb[4][2];
                const int xo = xbase + dh*72 + dw;
                #pragma unroll
                for (int f = 0; f < 4; f++) {
                    bb[f][0] = xsb[tig*XS_PLANE       + xo + 8*f];
                    bb[f][1] = xsb[(tig + 4)*XS_PLANE + xo + 8*f];
                }
                #pragma unroll
                for (int mf = 0; mf < 4; mf++)
                    #pragma unroll
                    for (int f = 0; f < 4; f++)
                        mma16(acc[mf][f], a[mf], bb[f]);
            }
        }
        __syncthreads();
    }

    const int hw = h0 + wr;
    #pragma unroll
    for (int mf = 0; mf < 4; mf++) {
        #pragma unroll
        for (int f = 0; f < 4; f++) {
            int co = co0 + 16*mf + g;
            int px = cw + 8*f + 2*tig;
            float* yp = y + (((size_t)b*CO_ + co)*H_ + hw)*W_ + px;
            *(float2*)yp             = make_float2(acc[mf][f][0], acc[mf][f][1]);
            *(float2*)(yp + 8*H_*W_) = make_float2(acc[mf][f][2], acc[mf][f][3]);
        }
    }
}

// ---------------------------------------------------------------------------
// Launch
// ---------------------------------------------------------------------------
extern "C" void kernel_launch(void* const* d_in, const int* in_sizes, int n_in,
                              void* d_out, int out_size) {
    const float* x  = (const float*)d_in[0];
    const float* tf = (const float*)d_in[1];
    const float* Wb = (const float*)d_in[2];
    float* y        = (float*)d_out;

    cudaFuncSetAttribute(k_conv, cudaFuncAttributeMaxDynamicSharedMemorySize, SMEM_BYTES);

    k_prep<<<NWB + NXB, 256>>>(x, tf, Wb);
    dim3 grid(8, 2, B_);
    k_conv<<<grid, 512, SMEM_BYTES>>>(y);
    (void)in_sizes; (void)n_in; (void)out_size;
}